// round 13
// baseline (speedup 1.0000x reference)
#include <cuda_runtime.h>
#include <cuda_bf16.h>
#include <math.h>
#include <stdint.h>

// Problem constants
#define BGRAPH 256
#define NNODE  256
#define DFEAT  128
#define KTOP   10
#define E_PER  8192
#define NUM_NODES (BGRAPH * NNODE)     // 65536
#define E_TOT (BGRAPH * E_PER)         // 2097152
#define OUT_CH 128
#define HALF_D 64
#define FULLMASK 0xffffffffu

// ---------------- scratch (device globals; no runtime allocation) -------------
__device__ float g_bufB[NUM_NODES * DFEAT];                       // fp32 h after layer 2
__device__ float g_od[NUM_NODES];
__device__ float g_id[NUM_NODES];
__device__ __nv_bfloat16 g_adj[(size_t)BGRAPH * NNODE * NNODE];   // 32 MB dense adjacency
__device__ __nv_bfloat16 g_hThi[(size_t)NUM_NODES * DFEAT];       // od*h transposed [g][f][node], hi
__device__ __nv_bfloat16 g_hTlo[(size_t)NUM_NODES * DFEAT];       // lo
__device__ __nv_bfloat16 g_Ahi[(size_t)NUM_NODES * DFEAT];        // agg out [m][k] bf16 hi
__device__ __nv_bfloat16 g_Alo[(size_t)NUM_NODES * DFEAT];        // lo
__device__ float g_key[NUM_NODES];
__device__ __nv_bfloat16 g_Wthi[3 * DFEAT * DFEAT];   // W transposed [n][k], bf16 hi
__device__ __nv_bfloat16 g_Wtlo[3 * DFEAT * DFEAT];   // W transposed [n][k], bf16 lo

__device__ __forceinline__ uint32_t smem_u32(const void* p) {
    uint32_t a;
    asm("{ .reg .u64 t; cvta.to.shared.u64 t, %1; cvt.u32.u64 %0, t; }" : "=r"(a) : "l"(p));
    return a;
}
__device__ __forceinline__ void ldmatrix_x4(unsigned& r0, unsigned& r1, unsigned& r2,
                                            unsigned& r3, uint32_t addr) {
    asm volatile("ldmatrix.sync.aligned.m8n8.x4.shared.b16 {%0,%1,%2,%3}, [%4];"
                 : "=r"(r0), "=r"(r1), "=r"(r2), "=r"(r3) : "r"(addr));
}
__device__ __forceinline__ unsigned pack_bf16(__nv_bfloat16 a, __nv_bfloat16 b) {
    return ((unsigned)__bfloat16_as_ushort(b) << 16) | __bfloat16_as_ushort(a);
}
__device__ __forceinline__ unsigned split_pack_hi(float x0, float x1,
                                                  __nv_bfloat16& h0, __nv_bfloat16& h1) {
    h0 = __float2bfloat16(x0);
    h1 = __float2bfloat16(x1);
    return pack_bf16(h0, h1);
}
__device__ __forceinline__ void cp_async16(uint32_t dst, const void* src) {
    asm volatile("cp.async.cg.shared.global [%0], [%1], 16;" :: "r"(dst), "l"(src) : "memory");
}
__device__ __forceinline__ void cp_commit() {
    asm volatile("cp.async.commit_group;" ::: "memory");
}
template <int N>
__device__ __forceinline__ void cp_wait() {
    asm volatile("cp.async.wait_group %0;" :: "n"(N) : "memory");
}

#define MMA_BF16(d, a, b0v, b1v)                                                 \
    asm volatile("mma.sync.aligned.m16n8k16.row.col.f32.bf16.bf16.f32 "          \
                 "{%0,%1,%2,%3}, {%4,%5,%6,%7}, {%8,%9}, {%0,%1,%2,%3};\n"       \
                 : "+f"(d[0]), "+f"(d[1]), "+f"(d[2]), "+f"(d[3])                \
                 : "r"(a[0]), "r"(a[1]), "r"(a[2]), "r"(a[3]), "r"(b0v), "r"(b1v))

#define KPAD 72            // bf16 row stride: 144B -> conflict-free ldmatrix
#define STAGE_BYTES (2 * (256 * KPAD + 2 * 64 * KPAD))   // 55296
#define TPAD 136           // epilogue transpose stride

// =============================================================================
// kernel 1: graph build via SHARED-memory histogram (no global atomics).
// =============================================================================
__global__ void build_kernel(const int* __restrict__ src, const int* __restrict__ dst) {
    extern __shared__ unsigned scnt[];    // [128][256]
    __shared__ unsigned sdout[256];
    int b = blockIdx.x, dh = blockIdx.y;
    int tid = threadIdx.x;
    int warp = tid >> 5, lane = tid & 31;

    for (int i = tid; i < 128 * 256; i += 256) scnt[i] = 0;
    sdout[tid] = 0;
    __syncthreads();

    int ebase = b * E_PER;
    #pragma unroll 4
    for (int j = 0; j < 32; j++) {
        int e = ebase + j * 256 + tid;
        int s = src[e] & 255;
        int d = dst[e] & 255;
        if (dh == 0) atomicAdd(&sdout[s], 1u);
        if ((d >> 7) == dh) atomicAdd(&scnt[(d & 127) * 256 + s], 1u);
    }
    __syncthreads();

    __nv_bfloat16* adjb = g_adj + (size_t)b * (NNODE * NNODE) + (size_t)dh * 128 * NNODE;
    unsigned* adj32 = (unsigned*)adjb;
    for (int i = tid; i < 128 * 256 / 2; i += 256) {
        unsigned c0 = scnt[2 * i], c1 = scnt[2 * i + 1];
        adj32[i] = pack_bf16(__float2bfloat16((float)c0), __float2bfloat16((float)c1));
    }

    for (int rr = 0; rr < 16; rr++) {
        int row = warp * 16 + rr;
        unsigned ssum = 0;
        #pragma unroll
        for (int q = 0; q < 8; q++) ssum += scnt[row * 256 + q * 32 + lane];
        #pragma unroll
        for (int off = 16; off; off >>= 1) ssum += __shfl_xor_sync(FULLMASK, ssum, off);
        if (lane == 0) {
            int gn = b * NNODE + dh * 128 + row;
            g_id[gn] = 1.0f / sqrtf((float)max((int)ssum, 1));
        }
    }
    if (dh == 0) {
        int gn = b * NNODE + tid;
        g_od[gn] = 1.0f / sqrtf((float)max((int)sdout[tid], 1));
    }
}

// =============================================================================
// kernel 2: hsplit — od*h -> bf16 hi/lo transposed (ONLY for the initial feats)
// =============================================================================
__global__ void hsplit_kernel(const float* __restrict__ h) {
    __shared__ float sh[64][132];
    int b = blockIdx.x;
    int tid = threadIdx.x;
    int gbase = b * NNODE;
    unsigned* hi32 = (unsigned*)g_hThi;
    unsigned* lo32 = (unsigned*)g_hTlo;

    for (int c = 0; c < 4; c++) {
        __syncthreads();
        #pragma unroll
        for (int j = 0; j < 8; j++) {
            int i = tid + j * 256;
            int node = i >> 5, f4 = i & 31;
            float od = g_od[gbase + c * 64 + node];
            float4 v = *(const float4*)&h[(size_t)(gbase + c * 64 + node) * DFEAT + f4 * 4];
            sh[node][f4 * 4 + 0] = v.x * od;
            sh[node][f4 * 4 + 1] = v.y * od;
            sh[node][f4 * 4 + 2] = v.z * od;
            sh[node][f4 * 4 + 3] = v.w * od;
        }
        __syncthreads();
        #pragma unroll
        for (int j = 0; j < 16; j++) {
            int i = tid + j * 256;
            int f = i >> 5, np = i & 31;
            float x0 = sh[2 * np][f], x1 = sh[2 * np + 1][f];
            __nv_bfloat16 h0, h1;
            size_t o = (((size_t)b * DFEAT + f) * NNODE + c * 64 + 2 * np) >> 1;
            hi32[o] = split_pack_hi(x0, x1, h0, h1);
            __nv_bfloat16 l0 = __float2bfloat16(x0 - __bfloat162float(h0));
            __nv_bfloat16 l1 = __float2bfloat16(x1 - __bfloat162float(h1));
            lo32[o] = pack_bf16(l0, l1);
        }
    }
}

// =============================================================================
// kernel 3: aggregation — cp.async double-buffered bf16 MMA.
// Epilogue now writes id*acc directly as bf16 hi/lo [m][k] (GEMM's A operand).
// =============================================================================
__global__ void __launch_bounds__(256, 2) agg_kernel(
    const __nv_bfloat16* __restrict__ hThi, const __nv_bfloat16* __restrict__ hTlo)
{
    extern __shared__ __nv_bfloat16 sm[];
    int b = blockIdx.x, half = blockIdx.y;
    int tid = threadIdx.x;
    int lane = tid & 31, warp = tid >> 5;
    int wm = warp >> 1, wn = warp & 1;
    int g = lane >> 2, t = lane & 3;
    int gbase = b * NNODE;
    const __nv_bfloat16* adjb = g_adj + (size_t)b * (NNODE * NNODE);
    const __nv_bfloat16* bhg = hThi + ((size_t)b * DFEAT + half * 64) * NNODE;
    const __nv_bfloat16* blg = hTlo + ((size_t)b * DFEAT + half * 64) * NNODE;

    uint32_t sbase = smem_u32(sm);
    const uint32_t BOFF = 2u * 256 * KPAD;
    const uint32_t LOFF = BOFF + 2u * 64 * KPAD;

    int ar = tid >> 3, aq = tid & 7;
    int bn = tid >> 3, bq = tid & 7;

    int lrow = lane & 15, lkh = lane >> 4;
    uint32_t aaddr[4], bhaddr[2], bladdr[2];
    #pragma unroll
    for (int mt = 0; mt < 4; mt++)
        aaddr[mt] = sbase + 2u * ((wm * 64 + mt * 16 + lrow) * KPAD + lkh * 8);
    #pragma unroll
    for (int j = 0; j < 2; j++) {
        bhaddr[j] = sbase + BOFF + 2u * ((wn * 32 + j * 16 + lrow) * KPAD + lkh * 8);
        bladdr[j] = sbase + LOFF + 2u * ((wn * 32 + j * 16 + lrow) * KPAD + lkh * 8);
    }

    float acc[4][4][4];
    #pragma unroll
    for (int mt = 0; mt < 4; mt++)
        #pragma unroll
        for (int nt = 0; nt < 4; nt++)
            #pragma unroll
            for (int q = 0; q < 4; q++) acc[mt][nt][q] = 0.f;

    #define ISSUE_STAGE(st, kc) do {                                              \
        uint32_t s0 = sbase + (uint32_t)(st) * STAGE_BYTES;                       \
        _Pragma("unroll")                                                         \
        for (int j = 0; j < 8; j++) {                                             \
            int r = ar + j * 32;                                                  \
            cp_async16(s0 + 2u * (r * KPAD + aq * 8),                             \
                       adjb + (size_t)r * NNODE + (kc) * 64 + aq * 8);            \
        }                                                                         \
        _Pragma("unroll")                                                         \
        for (int j = 0; j < 2; j++) {                                             \
            int n = bn + j * 32;                                                  \
            cp_async16(s0 + BOFF + 2u * (n * KPAD + bq * 8),                      \
                       bhg + (size_t)n * NNODE + (kc) * 64 + bq * 8);             \
            cp_async16(s0 + LOFF + 2u * (n * KPAD + bq * 8),                      \
                       blg + (size_t)n * NNODE + (kc) * 64 + bq * 8);             \
        }                                                                         \
        cp_commit();                                                              \
    } while (0)

    ISSUE_STAGE(0, 0);
    for (int kc = 0; kc < 4; kc++) {
        int cur = kc & 1;
        if (kc < 3) {
            ISSUE_STAGE(cur ^ 1, kc + 1);
            cp_wait<1>();
        } else {
            cp_wait<0>();
        }
        __syncthreads();
        uint32_t so = (uint32_t)cur * STAGE_BYTES;

        #pragma unroll
        for (int ks = 0; ks < 4; ks++) {
            uint32_t kb = so + 2u * (ks * 16);
            unsigned a[4][4];
            #pragma unroll
            for (int mt = 0; mt < 4; mt++)
                ldmatrix_x4(a[mt][0], a[mt][1], a[mt][2], a[mt][3], aaddr[mt] + kb);
            unsigned bh[2][4], bl[2][4];
            #pragma unroll
            for (int j = 0; j < 2; j++) {
                ldmatrix_x4(bh[j][0], bh[j][1], bh[j][2], bh[j][3], bhaddr[j] + kb);
                ldmatrix_x4(bl[j][0], bl[j][1], bl[j][2], bl[j][3], bladdr[j] + kb);
            }
            #pragma unroll
            for (int j = 0; j < 2; j++) {
                #pragma unroll
                for (int mt = 0; mt < 4; mt++) {
                    MMA_BF16(acc[mt][2 * j],     a[mt], bh[j][0], bh[j][2]);
                    MMA_BF16(acc[mt][2 * j + 1], a[mt], bh[j][1], bh[j][3]);
                    MMA_BF16(acc[mt][2 * j],     a[mt], bl[j][0], bl[j][2]);
                    MMA_BF16(acc[mt][2 * j + 1], a[mt], bl[j][1], bl[j][3]);
                }
            }
        }
        __syncthreads();
    }
    #undef ISSUE_STAGE

    // epilogue: id * acc -> bf16 hi/lo [m][k] (packed u32 stores)
    unsigned* ahi32 = (unsigned*)g_Ahi;
    unsigned* alo32 = (unsigned*)g_Alo;
    #pragma unroll
    for (int mt = 0; mt < 4; mt++) {
        int m = wm * 64 + mt * 16 + g;
        float id0 = g_id[gbase + m];
        float id1 = g_id[gbase + m + 8];
        #pragma unroll
        for (int nt = 0; nt < 4; nt++) {
            int n = half * HALF_D + wn * 32 + nt * 8 + 2 * t;
            float v00 = acc[mt][nt][0] * id0, v01 = acc[mt][nt][1] * id0;
            float v10 = acc[mt][nt][2] * id1, v11 = acc[mt][nt][3] * id1;
            __nv_bfloat16 h00, h01, h10, h11;
            size_t o0 = ((size_t)(gbase + m) * DFEAT + n) >> 1;
            size_t o1 = ((size_t)(gbase + m + 8) * DFEAT + n) >> 1;
            ahi32[o0] = split_pack_hi(v00, v01, h00, h01);
            ahi32[o1] = split_pack_hi(v10, v11, h10, h11);
            alo32[o0] = pack_bf16(__float2bfloat16(v00 - __bfloat162float(h00)),
                                  __float2bfloat16(v01 - __bfloat162float(h01)));
            alo32[o1] = pack_bf16(__float2bfloat16(v10 - __bfloat162float(h10)),
                                  __float2bfloat16(v11 - __bfloat162float(h11)));
        }
    }
}

// =============================================================================
// kernel 4: W -> W^T bf16 hi/lo split (one launch, all 3 layers)
// =============================================================================
__global__ void wsplit_kernel(const float* __restrict__ W0, const float* __restrict__ W1,
                              const float* __restrict__ W2) {
    int layer = blockIdx.x >> 6;
    int i = (blockIdx.x & 63) * 256 + threadIdx.x;   // i = k*128 + n
    const float* W = (layer == 0) ? W0 : ((layer == 1) ? W1 : W2);
    float x = W[i];
    int k = i >> 7, n = i & 127;
    __nv_bfloat16 hi = __float2bfloat16(x);
    __nv_bfloat16 lo = __float2bfloat16(x - __bfloat162float(hi));
    g_Wthi[layer * 16384 + n * 128 + k] = hi;
    g_Wtlo[layer * 16384 + n * 128 + k] = lo;
}

// =============================================================================
// kernel 5: bf16 3-pass GEMM + bias + relu. A pre-split (pure uint4 tile loads).
// WRITE_HT=true  (layers 0,1): epilogue writes od*h transposed bf16 hi/lo.
// WRITE_HT=false (layer 2):    fp32 C write + fused row-max key.
// =============================================================================
template <bool WRITE_HT>
__global__ void __launch_bounds__(256, 2) gemm_bf16_kernel(
    const __nv_bfloat16* __restrict__ ahi, const __nv_bfloat16* __restrict__ alo,
    const __nv_bfloat16* __restrict__ wthi, const __nv_bfloat16* __restrict__ wtlo,
    const float* __restrict__ bias, float* __restrict__ C)
{
    extern __shared__ __nv_bfloat16 sm[];
    __nv_bfloat16* sAh = sm;
    __nv_bfloat16* sAl = sAh + 128 * KPAD;
    __nv_bfloat16* sBh = sAl + 128 * KPAD;
    __nv_bfloat16* sBl = sBh + 128 * KPAD;
    __shared__ float sbias[128];
    __shared__ int skey[128];

    int tid = threadIdx.x;
    int lane = tid & 31, warp = tid >> 5;
    int wm = warp >> 1, wn = warp & 1;
    int g = lane >> 2, t = lane & 3;
    int m0 = blockIdx.x * 128;

    if (tid < 128) { sbias[tid] = bias[tid]; skey[tid] = 0; }

    int lrow = lane & 15, lkh = lane >> 4;
    uint32_t sAh_u = smem_u32(sAh), sAl_u = smem_u32(sAl);
    uint32_t sBh_u = smem_u32(sBh), sBl_u = smem_u32(sBl);
    uint32_t ahaddr[2], aladdr[2], bhaddr[4], bladdr[4];
    #pragma unroll
    for (int mt = 0; mt < 2; mt++) {
        uint32_t off = 2u * ((wm * 32 + mt * 16 + lrow) * KPAD + lkh * 8);
        ahaddr[mt] = sAh_u + off;
        aladdr[mt] = sAl_u + off;
    }
    #pragma unroll
    for (int j = 0; j < 4; j++) {
        uint32_t off = 2u * ((wn * 64 + j * 16 + lrow) * KPAD + lkh * 8);
        bhaddr[j] = sBh_u + off;
        bladdr[j] = sBl_u + off;
    }

    float acc[2][8][4];
    #pragma unroll
    for (int mt = 0; mt < 2; mt++)
        #pragma unroll
        for (int nt = 0; nt < 8; nt++)
            #pragma unroll
            for (int q = 0; q < 4; q++) acc[mt][nt][q] = 0.f;

    for (int kc = 0; kc < 2; kc++) {
        __syncthreads();
        // A chunk: pre-split, pure uint4 copies (128 rows x 64 k)
        #pragma unroll
        for (int j = 0; j < 4; j++) {
            int i = tid + j * 256;
            int r = i >> 3, q = i & 7;
            *(uint4*)(sAh + r * KPAD + q * 8) =
                *(const uint4*)(ahi + (size_t)(m0 + r) * 128 + kc * 64 + q * 8);
            *(uint4*)(sAl + r * KPAD + q * 8) =
                *(const uint4*)(alo + (size_t)(m0 + r) * 128 + kc * 64 + q * 8);
        }
        // B chunk: pre-split W^T, pure uint4 copies (128 rows x 64 k)
        #pragma unroll
        for (int j = 0; j < 4; j++) {
            int i = tid + j * 256;
            int n = i >> 3, q = i & 7;
            *(uint4*)(sBh + n * KPAD + q * 8) = *(const uint4*)(wthi + n * 128 + kc * 64 + q * 8);
            *(uint4*)(sBl + n * KPAD + q * 8) = *(const uint4*)(wtlo + n * 128 + kc * 64 + q * 8);
        }
        __syncthreads();

        #pragma unroll
        for (int ks = 0; ks < 4; ks++) {
            uint32_t kb = 2u * (ks * 16);
            unsigned ah[2][4], al[2][4];
            #pragma unroll
            for (int mt = 0; mt < 2; mt++) {
                ldmatrix_x4(ah[mt][0], ah[mt][1], ah[mt][2], ah[mt][3], ahaddr[mt] + kb);
                ldmatrix_x4(al[mt][0], al[mt][1], al[mt][2], al[mt][3], aladdr[mt] + kb);
            }
            #pragma unroll
            for (int jh = 0; jh < 2; jh++) {
                unsigned bh[2][4], bl[2][4];
                #pragma unroll
                for (int jj = 0; jj < 2; jj++) {
                    int j = jh * 2 + jj;
                    ldmatrix_x4(bh[jj][0], bh[jj][1], bh[jj][2], bh[jj][3], bhaddr[j] + kb);
                    ldmatrix_x4(bl[jj][0], bl[jj][1], bl[jj][2], bl[jj][3], bladdr[j] + kb);
                }
                #pragma unroll
                for (int jj = 0; jj < 2; jj++) {
                    int j = jh * 2 + jj;
                    #pragma unroll
                    for (int mt = 0; mt < 2; mt++) {
                        MMA_BF16(acc[mt][2 * j],     ah[mt], bh[jj][0], bh[jj][2]);
                        MMA_BF16(acc[mt][2 * j + 1], ah[mt], bh[jj][1], bh[jj][3]);
                        MMA_BF16(acc[mt][2 * j],     ah[mt], bl[jj][0], bl[jj][2]);
                        MMA_BF16(acc[mt][2 * j + 1], ah[mt], bl[jj][1], bl[jj][3]);
                        MMA_BF16(acc[mt][2 * j],     al[mt], bh[jj][0], bh[jj][2]);
                        MMA_BF16(acc[mt][2 * j + 1], al[mt], bh[jj][1], bh[jj][3]);
                    }
                }
            }
        }
    }

    if (WRITE_HT) {
        // epilogue: od * relu(acc + bias), bf16 split, smem transpose -> hT
        __syncthreads();
        __nv_bfloat16* sThi = sm;                   // [128 f][TPAD]
        __nv_bfloat16* sTlo = sm + 128 * TPAD;
        #pragma unroll
        for (int mt = 0; mt < 2; mt++) {
            int ml0 = wm * 32 + mt * 16 + g;
            float od0 = g_od[m0 + ml0];
            float od1 = g_od[m0 + ml0 + 8];
            #pragma unroll
            for (int nt = 0; nt < 8; nt++) {
                int n = wn * 64 + nt * 8 + 2 * t;
                float b0v = sbias[n], b1v = sbias[n + 1];
                float v00 = fmaxf(acc[mt][nt][0] + b0v, 0.f) * od0;
                float v01 = fmaxf(acc[mt][nt][1] + b1v, 0.f) * od0;
                float v10 = fmaxf(acc[mt][nt][2] + b0v, 0.f) * od1;
                float v11 = fmaxf(acc[mt][nt][3] + b1v, 0.f) * od1;
                __nv_bfloat16 h00 = __float2bfloat16(v00);
                __nv_bfloat16 h01 = __float2bfloat16(v01);
                __nv_bfloat16 h10 = __float2bfloat16(v10);
                __nv_bfloat16 h11 = __float2bfloat16(v11);
                sThi[n * TPAD + ml0] = h00;
                sThi[(n + 1) * TPAD + ml0] = h01;
                sThi[n * TPAD + ml0 + 8] = h10;
                sThi[(n + 1) * TPAD + ml0 + 8] = h11;
                sTlo[n * TPAD + ml0] = __float2bfloat16(v00 - __bfloat162float(h00));
                sTlo[(n + 1) * TPAD + ml0] = __float2bfloat16(v01 - __bfloat162float(h01));
                sTlo[n * TPAD + ml0 + 8] = __float2bfloat16(v10 - __bfloat162float(h10));
                sTlo[(n + 1) * TPAD + ml0 + 8] = __float2bfloat16(v11 - __bfloat162float(h11));
            }
        }
        __syncthreads();
        int bg = blockIdx.x >> 1;
        int nb = (blockIdx.x & 1) * 128;
        unsigned* hi32 = (unsigned*)g_hThi;
        unsigned* lo32 = (unsigned*)g_hTlo;
        #pragma unroll
        for (int j = 0; j < 32; j++) {
            int i = tid + j * 256;                   // 0..8191
            int f = i >> 6, np = i & 63;
            unsigned hv = *(unsigned*)&sThi[f * TPAD + 2 * np];
            unsigned lv = *(unsigned*)&sTlo[f * TPAD + 2 * np];
            size_t o = (((size_t)bg * DFEAT + f) * NNODE + nb + 2 * np) >> 1;
            hi32[o] = hv;
            lo32[o] = lv;
        }
    } else {
        // epilogue: fp32 C store + fused row-max key
        __syncthreads();   // skey init visible
        #pragma unroll
        for (int mt = 0; mt < 2; mt++) {
            int m = m0 + wm * 32 + mt * 16 + g;
            float mx0 = 0.f, mx1 = 0.f;
            #pragma unroll
            for (int nt = 0; nt < 8; nt++) {
                int n = wn * 64 + nt * 8 + 2 * t;
                float b0v = sbias[n], b1v = sbias[n + 1];
                float2 o0, o1;
                o0.x = fmaxf(acc[mt][nt][0] + b0v, 0.f);
                o0.y = fmaxf(acc[mt][nt][1] + b1v, 0.f);
                o1.x = fmaxf(acc[mt][nt][2] + b0v, 0.f);
                o1.y = fmaxf(acc[mt][nt][3] + b1v, 0.f);
                mx0 = fmaxf(mx0, fmaxf(o0.x, o0.y));
                mx1 = fmaxf(mx1, fmaxf(o1.x, o1.y));
                *(float2*)&C[(size_t)m * 128 + n] = o0;
                *(float2*)&C[(size_t)(m + 8) * 128 + n] = o1;
            }
            atomicMax(&skey[wm * 32 + mt * 16 + g], __float_as_int(mx0));
            atomicMax(&skey[wm * 32 + mt * 16 + g + 8], __float_as_int(mx1));
        }
        __syncthreads();
        if (tid < 128) g_key[m0 + tid] = __int_as_float(skey[tid]);
    }
}

// =============================================================================
// kernel 6: fused tail — topk (warp 0) + bitonic sort of 10 rows + conv head.
// Block = one graph, 256 threads. Pooled rows never touch global memory.
// =============================================================================
__global__ void tail_kernel(const float* __restrict__ w1, const float* __restrict__ b1c,
                            const float* __restrict__ w2, const float* __restrict__ b2c,
                            float* __restrict__ out)
{
    int b = blockIdx.x;
    int tid = threadIdx.x;   // 256
    __shared__ int stopk[KTOP];
    __shared__ float sp[KTOP][132];
    __shared__ float sw1[64][132];
    __shared__ float sc1[64][KTOP];
    __shared__ float sc1p[64][5];

    // warp 0: exact lax.top_k over the 256 keys
    if (tid < 32) {
        int lane = tid;
        float v[8];
        #pragma unroll
        for (int r = 0; r < 8; r++) v[r] = g_key[b * NNODE + r * 32 + lane];
        for (int t = 0; t < KTOP; t++) {
            float bv = -INFINITY;
            int bi = 0;
            #pragma unroll
            for (int r = 0; r < 8; r++) {
                int idx = r * 32 + lane;
                if (v[r] > bv || (v[r] == bv && idx < bi)) { bv = v[r]; bi = idx; }
            }
            #pragma unroll
            for (int off = 16; off; off >>= 1) {
                float ov = __shfl_xor_sync(FULLMASK, bv, off);
                int   oi = __shfl_xor_sync(FULLMASK, bi, off);
                if (ov > bv || (ov == bv && oi < bi)) { bv = ov; bi = oi; }
            }
            if (lane == 0) stopk[t] = bi;
            if (lane == (bi & 31)) v[bi >> 5] = -INFINITY;
        }
    }
    // meanwhile: load conv1 weights
    for (int i = tid; i < 64 * DFEAT; i += 256)
        sw1[i / DFEAT][i % DFEAT] = w1[i];
    __syncthreads();

    // load the 10 selected rows
    int grp = tid >> 7, t7 = tid & 127;
    for (int rr = grp; rr < KTOP; rr += 2) {
        int node = stopk[rr];
        sp[rr][t7] = g_bufB[(size_t)(b * NNODE + node) * DFEAT + t7];
    }
    __syncthreads();

    // bitonic sort each row ascending (2 rows in parallel, 5 passes)
    for (int it = 0; it < 5; it++) {
        int row = grp + 2 * it;
        float* s = &sp[row][0];
        for (int k = 2; k <= 128; k <<= 1) {
            for (int j = k >> 1; j > 0; j >>= 1) {
                int p = t7 ^ j;
                if (p > t7) {
                    bool up = ((t7 & k) == 0);
                    float a = s[t7], c = s[p];
                    if ((a > c) == up) { s[t7] = c; s[p] = a; }
                }
                __syncthreads();
            }
        }
    }

    // conv1: c1[oc][k] = relu(b1[oc] + dot(sp[k], w1[oc]))
    for (int o = tid; o < 64 * KTOP; o += 256) {
        int oc = o / KTOP, k = o % KTOP;
        float acc = b1c[oc];
        #pragma unroll 8
        for (int d = 0; d < DFEAT; d++) acc += sp[k][d] * sw1[oc][d];
        sc1[oc][k] = fmaxf(acc, 0.f);
    }
    __syncthreads();
    for (int o = tid; o < 64 * 5; o += 256) {
        int ic = o / 5, t = o % 5;
        sc1p[ic][t] = fmaxf(sc1[ic][2 * t], sc1[ic][2 * t + 1]);
    }
    __syncthreads();
    if (tid < 128) {
        float acc = b2c[tid];
        const float* wrow = w2 + tid * 320;
        const float* cp = &sc1p[0][0];
        #pragma unroll 8
        for (int q = 0; q < 320; q++) acc += cp[q] * wrow[q];
        out[b * OUT_CH + tid] = fmaxf(acc, 0.f);
    }
}

// ---------------- launcher ---------------------------------------------------
extern "C" void kernel_launch(void* const* d_in, const int* in_sizes, int n_in,
                              void* d_out, int out_size)
{
    const float* feats   = (const float*)d_in[0];
    const int*   src     = (const int*)d_in[1];
    const int*   dst     = (const int*)d_in[2];
    const float* W0      = (const float*)d_in[3];
    const float* b0      = (const float*)d_in[4];
    const float* W1      = (const float*)d_in[5];
    const float* b1      = (const float*)d_in[6];
    const float* W2      = (const float*)d_in[7];
    const float* b2      = (const float*)d_in[8];
    const float* conv1_w = (const float*)d_in[9];
    const float* conv1_b = (const float*)d_in[10];
    const float* conv2_w = (const float*)d_in[11];
    const float* conv2_b = (const float*)d_in[12];
    float* out = (float*)d_out;

    int build_smem = 128 * 256 * 4;              // 131072
    int agg_smem   = 2 * STAGE_BYTES;            // 110592
    int gemm_smem  = 4 * 128 * KPAD * 2;         // 73728 (>= 2*128*TPAD*2 = 69632)
    cudaFuncSetAttribute(build_kernel, cudaFuncAttributeMaxDynamicSharedMemorySize, build_smem);
    cudaFuncSetAttribute(agg_kernel, cudaFuncAttributeMaxDynamicSharedMemorySize, agg_smem);
    cudaFuncSetAttribute(gemm_bf16_kernel<true>, cudaFuncAttributeMaxDynamicSharedMemorySize, gemm_smem);
    cudaFuncSetAttribute(gemm_bf16_kernel<false>, cudaFuncAttributeMaxDynamicSharedMemorySize, gemm_smem);

    float* bufB;  cudaGetSymbolAddress((void**)&bufB, g_bufB);
    __nv_bfloat16* wthi;  cudaGetSymbolAddress((void**)&wthi, g_Wthi);
    __nv_bfloat16* wtlo;  cudaGetSymbolAddress((void**)&wtlo, g_Wtlo);
    __nv_bfloat16* hthi;  cudaGetSymbolAddress((void**)&hthi, g_hThi);
    __nv_bfloat16* htlo;  cudaGetSymbolAddress((void**)&htlo, g_hTlo);
    __nv_bfloat16* ahi;   cudaGetSymbolAddress((void**)&ahi, g_Ahi);
    __nv_bfloat16* alo;   cudaGetSymbolAddress((void**)&alo, g_Alo);

    build_kernel<<<dim3(BGRAPH, 2), 256, build_smem>>>(src, dst);
    wsplit_kernel<<<192, 256>>>(W0, W1, W2);
    hsplit_kernel<<<BGRAPH, 256>>>(feats);

    dim3 agg_grid(BGRAPH, 2);
    // layer 0
    agg_kernel<<<agg_grid, 256, agg_smem>>>(hthi, htlo);
    gemm_bf16_kernel<true><<<NUM_NODES / 128, 256, gemm_smem>>>(ahi, alo, wthi, wtlo, b0, nullptr);
    // layer 1
    agg_kernel<<<agg_grid, 256, agg_smem>>>(hthi, htlo);
    gemm_bf16_kernel<true><<<NUM_NODES / 128, 256, gemm_smem>>>(ahi, alo, wthi + 16384, wtlo + 16384, b1, nullptr);
    // layer 2: fp32 out + fused key
    agg_kernel<<<agg_grid, 256, agg_smem>>>(hthi, htlo);
    gemm_bf16_kernel<false><<<NUM_NODES / 128, 256, gemm_smem>>>(ahi, alo, wthi + 32768, wtlo + 32768, b2, bufB);

    tail_kernel<<<BGRAPH, 256>>>(conv1_w, conv1_b, conv2_w, conv2_b, out);
}

// round 15
// speedup vs baseline: 1.0284x; 1.0284x over previous
#include <cuda_runtime.h>
#include <cuda_bf16.h>
#include <math.h>
#include <stdint.h>

// Problem constants
#define BGRAPH 256
#define NNODE  256
#define DFEAT  128
#define KTOP   10
#define E_PER  8192
#define NUM_NODES (BGRAPH * NNODE)     // 65536
#define E_TOT (BGRAPH * E_PER)         // 2097152
#define OUT_CH 128
#define HALF_D 64
#define FULLMASK 0xffffffffu

// ---------------- scratch (device globals; no runtime allocation) -------------
__device__ float g_bufA[NUM_NODES * DFEAT];                       // agg output (fp32)
__device__ float g_bufB[NUM_NODES * DFEAT];                       // fp32 h after layer 2
__device__ float g_od[NUM_NODES];
__device__ float g_id[NUM_NODES];
__device__ __nv_bfloat16 g_adj[(size_t)BGRAPH * NNODE * NNODE];   // 32 MB dense adjacency
__device__ __nv_bfloat16 g_hThi[(size_t)NUM_NODES * DFEAT];       // od*h transposed [g][f][node], hi
__device__ __nv_bfloat16 g_hTlo[(size_t)NUM_NODES * DFEAT];       // lo
__device__ float g_key[NUM_NODES];
__device__ __nv_bfloat16 g_Wthi[3 * DFEAT * DFEAT];   // W transposed [n][k], bf16 hi
__device__ __nv_bfloat16 g_Wtlo[3 * DFEAT * DFEAT];   // W transposed [n][k], bf16 lo

__device__ __forceinline__ uint32_t smem_u32(const void* p) {
    uint32_t a;
    asm("{ .reg .u64 t; cvta.to.shared.u64 t, %1; cvt.u32.u64 %0, t; }" : "=r"(a) : "l"(p));
    return a;
}
__device__ __forceinline__ void ldmatrix_x4(unsigned& r0, unsigned& r1, unsigned& r2,
                                            unsigned& r3, uint32_t addr) {
    asm volatile("ldmatrix.sync.aligned.m8n8.x4.shared.b16 {%0,%1,%2,%3}, [%4];"
                 : "=r"(r0), "=r"(r1), "=r"(r2), "=r"(r3) : "r"(addr));
}
__device__ __forceinline__ unsigned pack_bf16(__nv_bfloat16 a, __nv_bfloat16 b) {
    return ((unsigned)__bfloat16_as_ushort(b) << 16) | __bfloat16_as_ushort(a);
}
__device__ __forceinline__ void cp_async16(uint32_t dst, const void* src) {
    asm volatile("cp.async.cg.shared.global [%0], [%1], 16;" :: "r"(dst), "l"(src) : "memory");
}
__device__ __forceinline__ void cp_commit() {
    asm volatile("cp.async.commit_group;" ::: "memory");
}
template <int N>
__device__ __forceinline__ void cp_wait() {
    asm volatile("cp.async.wait_group %0;" :: "n"(N) : "memory");
}

#define MMA_BF16(d, a, b0v, b1v)                                                 \
    asm volatile("mma.sync.aligned.m16n8k16.row.col.f32.bf16.bf16.f32 "          \
                 "{%0,%1,%2,%3}, {%4,%5,%6,%7}, {%8,%9}, {%0,%1,%2,%3};\n"       \
                 : "+f"(d[0]), "+f"(d[1]), "+f"(d[2]), "+f"(d[3])                \
                 : "r"(a[0]), "r"(a[1]), "r"(a[2]), "r"(a[3]), "r"(b0v), "r"(b1v))

#define KPAD 72            // bf16 row stride: 144B -> conflict-free ldmatrix
#define STAGE_BYTES (2 * (256 * KPAD + 2 * 64 * KPAD))   // 55296
#define TPAD 136           // epilogue transpose stride

// =============================================================================
// kernel 1: graph build via SHARED-memory histogram (no global atomics).
// =============================================================================
__global__ void build_kernel(const int* __restrict__ src, const int* __restrict__ dst) {
    extern __shared__ unsigned scnt[];    // [128][256]
    __shared__ unsigned sdout[256];
    int b = blockIdx.x, dh = blockIdx.y;
    int tid = threadIdx.x;
    int warp = tid >> 5, lane = tid & 31;

    for (int i = tid; i < 128 * 256; i += 256) scnt[i] = 0;
    sdout[tid] = 0;
    __syncthreads();

    int ebase = b * E_PER;
    #pragma unroll 4
    for (int j = 0; j < 32; j++) {
        int e = ebase + j * 256 + tid;
        int s = src[e] & 255;
        int d = dst[e] & 255;
        if (dh == 0) atomicAdd(&sdout[s], 1u);
        if ((d >> 7) == dh) atomicAdd(&scnt[(d & 127) * 256 + s], 1u);
    }
    __syncthreads();

    __nv_bfloat16* adjb = g_adj + (size_t)b * (NNODE * NNODE) + (size_t)dh * 128 * NNODE;
    unsigned* adj32 = (unsigned*)adjb;
    for (int i = tid; i < 128 * 256 / 2; i += 256) {
        unsigned c0 = scnt[2 * i], c1 = scnt[2 * i + 1];
        adj32[i] = pack_bf16(__float2bfloat16((float)c0), __float2bfloat16((float)c1));
    }

    for (int rr = 0; rr < 16; rr++) {
        int row = warp * 16 + rr;
        unsigned ssum = 0;
        #pragma unroll
        for (int q = 0; q < 8; q++) ssum += scnt[row * 256 + q * 32 + lane];
        #pragma unroll
        for (int off = 16; off; off >>= 1) ssum += __shfl_xor_sync(FULLMASK, ssum, off);
        if (lane == 0) {
            int gn = b * NNODE + dh * 128 + row;
            g_id[gn] = 1.0f / sqrtf((float)max((int)ssum, 1));
        }
    }
    if (dh == 0) {
        int gn = b * NNODE + tid;
        g_od[gn] = 1.0f / sqrtf((float)max((int)sdout[tid], 1));
    }
}

// =============================================================================
// kernel 2: hsplit — od*h -> bf16 hi/lo transposed (ONLY for the initial feats)
// =============================================================================
__global__ void hsplit_kernel(const float* __restrict__ h) {
    __shared__ float sh[64][132];
    int b = blockIdx.x;
    int tid = threadIdx.x;
    int gbase = b * NNODE;
    unsigned* hi32 = (unsigned*)g_hThi;
    unsigned* lo32 = (unsigned*)g_hTlo;

    for (int c = 0; c < 4; c++) {
        __syncthreads();
        #pragma unroll
        for (int j = 0; j < 8; j++) {
            int i = tid + j * 256;
            int node = i >> 5, f4 = i & 31;
            float od = g_od[gbase + c * 64 + node];
            float4 v = *(const float4*)&h[(size_t)(gbase + c * 64 + node) * DFEAT + f4 * 4];
            sh[node][f4 * 4 + 0] = v.x * od;
            sh[node][f4 * 4 + 1] = v.y * od;
            sh[node][f4 * 4 + 2] = v.z * od;
            sh[node][f4 * 4 + 3] = v.w * od;
        }
        __syncthreads();
        #pragma unroll
        for (int j = 0; j < 16; j++) {
            int i = tid + j * 256;
            int f = i >> 5, np = i & 31;
            float x0 = sh[2 * np][f], x1 = sh[2 * np + 1][f];
            __nv_bfloat16 h0 = __float2bfloat16(x0);
            __nv_bfloat16 h1 = __float2bfloat16(x1);
            size_t o = (((size_t)b * DFEAT + f) * NNODE + c * 64 + 2 * np) >> 1;
            hi32[o] = pack_bf16(h0, h1);
            __nv_bfloat16 l0 = __float2bfloat16(x0 - __bfloat162float(h0));
            __nv_bfloat16 l1 = __float2bfloat16(x1 - __bfloat162float(h1));
            lo32[o] = pack_bf16(l0, l1);
        }
    }
}

// =============================================================================
// kernel 3: aggregation — cp.async double-buffered bf16 MMA (R12 version,
// measured 41.5us/launch: fp32 id*acc epilogue, no split).
// =============================================================================
__global__ void __launch_bounds__(256, 2) agg_kernel(
    const __nv_bfloat16* __restrict__ hThi, const __nv_bfloat16* __restrict__ hTlo,
    float* __restrict__ out)
{
    extern __shared__ __nv_bfloat16 sm[];
    int b = blockIdx.x, half = blockIdx.y;
    int tid = threadIdx.x;
    int lane = tid & 31, warp = tid >> 5;
    int wm = warp >> 1, wn = warp & 1;
    int g = lane >> 2, t = lane & 3;
    int gbase = b * NNODE;
    const __nv_bfloat16* adjb = g_adj + (size_t)b * (NNODE * NNODE);
    const __nv_bfloat16* bhg = hThi + ((size_t)b * DFEAT + half * 64) * NNODE;
    const __nv_bfloat16* blg = hTlo + ((size_t)b * DFEAT + half * 64) * NNODE;

    uint32_t sbase = smem_u32(sm);
    const uint32_t BOFF = 2u * 256 * KPAD;
    const uint32_t LOFF = BOFF + 2u * 64 * KPAD;

    int ar = tid >> 3, aq = tid & 7;
    int bn = tid >> 3, bq = tid & 7;

    int lrow = lane & 15, lkh = lane >> 4;
    uint32_t aaddr[4], bhaddr[2], bladdr[2];
    #pragma unroll
    for (int mt = 0; mt < 4; mt++)
        aaddr[mt] = sbase + 2u * ((wm * 64 + mt * 16 + lrow) * KPAD + lkh * 8);
    #pragma unroll
    for (int j = 0; j < 2; j++) {
        bhaddr[j] = sbase + BOFF + 2u * ((wn * 32 + j * 16 + lrow) * KPAD + lkh * 8);
        bladdr[j] = sbase + LOFF + 2u * ((wn * 32 + j * 16 + lrow) * KPAD + lkh * 8);
    }

    float acc[4][4][4];
    #pragma unroll
    for (int mt = 0; mt < 4; mt++)
        #pragma unroll
        for (int nt = 0; nt < 4; nt++)
            #pragma unroll
            for (int q = 0; q < 4; q++) acc[mt][nt][q] = 0.f;

    #define ISSUE_STAGE(st, kc) do {                                              \
        uint32_t s0 = sbase + (uint32_t)(st) * STAGE_BYTES;                       \
        _Pragma("unroll")                                                         \
        for (int j = 0; j < 8; j++) {                                             \
            int r = ar + j * 32;                                                  \
            cp_async16(s0 + 2u * (r * KPAD + aq * 8),                             \
                       adjb + (size_t)r * NNODE + (kc) * 64 + aq * 8);            \
        }                                                                         \
        _Pragma("unroll")                                                         \
        for (int j = 0; j < 2; j++) {                                             \
            int n = bn + j * 32;                                                  \
            cp_async16(s0 + BOFF + 2u * (n * KPAD + bq * 8),                      \
                       bhg + (size_t)n * NNODE + (kc) * 64 + bq * 8);             \
            cp_async16(s0 + LOFF + 2u * (n * KPAD + bq * 8),                      \
                       blg + (size_t)n * NNODE + (kc) * 64 + bq * 8);             \
        }                                                                         \
        cp_commit();                                                              \
    } while (0)

    ISSUE_STAGE(0, 0);
    for (int kc = 0; kc < 4; kc++) {
        int cur = kc & 1;
        if (kc < 3) {
            ISSUE_STAGE(cur ^ 1, kc + 1);
            cp_wait<1>();
        } else {
            cp_wait<0>();
        }
        __syncthreads();
        uint32_t so = (uint32_t)cur * STAGE_BYTES;

        #pragma unroll
        for (int ks = 0; ks < 4; ks++) {
            uint32_t kb = so + 2u * (ks * 16);
            unsigned a[4][4];
            #pragma unroll
            for (int mt = 0; mt < 4; mt++)
                ldmatrix_x4(a[mt][0], a[mt][1], a[mt][2], a[mt][3], aaddr[mt] + kb);
            unsigned bh[2][4], bl[2][4];
            #pragma unroll
            for (int j = 0; j < 2; j++) {
                ldmatrix_x4(bh[j][0], bh[j][1], bh[j][2], bh[j][3], bhaddr[j] + kb);
                ldmatrix_x4(bl[j][0], bl[j][1], bl[j][2], bl[j][3], bladdr[j] + kb);
            }
            #pragma unroll
            for (int j = 0; j < 2; j++) {
                #pragma unroll
                for (int mt = 0; mt < 4; mt++) {
                    MMA_BF16(acc[mt][2 * j],     a[mt], bh[j][0], bh[j][2]);
                    MMA_BF16(acc[mt][2 * j + 1], a[mt], bh[j][1], bh[j][3]);
                    MMA_BF16(acc[mt][2 * j],     a[mt], bl[j][0], bl[j][2]);
                    MMA_BF16(acc[mt][2 * j + 1], a[mt], bl[j][1], bl[j][3]);
                }
            }
        }
        __syncthreads();
    }
    #undef ISSUE_STAGE

    #pragma unroll
    for (int mt = 0; mt < 4; mt++) {
        int m = wm * 64 + mt * 16 + g;
        float id0 = g_id[gbase + m];
        float id1 = g_id[gbase + m + 8];
        #pragma unroll
        for (int nt = 0; nt < 4; nt++) {
            int n = half * HALF_D + wn * 32 + nt * 8 + 2 * t;
            float2 o0, o1;
            o0.x = acc[mt][nt][0] * id0; o0.y = acc[mt][nt][1] * id0;
            o1.x = acc[mt][nt][2] * id1; o1.y = acc[mt][nt][3] * id1;
            *(float2*)&out[(size_t)(gbase + m) * DFEAT + n] = o0;
            *(float2*)&out[(size_t)(gbase + m + 8) * DFEAT + n] = o1;
        }
    }
}

// =============================================================================
// kernel 4: W -> W^T bf16 hi/lo split (one launch, all 3 layers)
// =============================================================================
__global__ void wsplit_kernel(const float* __restrict__ W0, const float* __restrict__ W1,
                              const float* __restrict__ W2) {
    int layer = blockIdx.x >> 6;
    int i = (blockIdx.x & 63) * 256 + threadIdx.x;   // i = k*128 + n
    const float* W = (layer == 0) ? W0 : ((layer == 1) ? W1 : W2);
    float x = W[i];
    int k = i >> 7, n = i & 127;
    __nv_bfloat16 hi = __float2bfloat16(x);
    __nv_bfloat16 lo = __float2bfloat16(x - __bfloat162float(hi));
    g_Wthi[layer * 16384 + n * 128 + k] = hi;
    g_Wtlo[layer * 16384 + n * 128 + k] = lo;
}

// =============================================================================
// kernel 5: bf16 3-pass GEMM + bias + relu (R12 version: fp32 A, in-kernel split)
// WRITE_HT=true  (layers 0,1): epilogue writes od*h transposed bf16 hi/lo.
// WRITE_HT=false (layer 2):    fp32 C write + fused row-max key.
// =============================================================================
template <bool WRITE_HT>
__global__ void __launch_bounds__(256, 2) gemm_bf16_kernel(
    const float* __restrict__ A,
    const __nv_bfloat16* __restrict__ wthi, const __nv_bfloat16* __restrict__ wtlo,
    const float* __restrict__ bias, float* __restrict__ C)
{
    extern __shared__ __nv_bfloat16 sm[];
    __nv_bfloat16* sAh = sm;
    __nv_bfloat16* sAl = sAh + 128 * KPAD;
    __nv_bfloat16* sBh = sAl + 128 * KPAD;
    __nv_bfloat16* sBl = sBh + 128 * KPAD;
    __shared__ float sbias[128];
    __shared__ int skey[128];

    int tid = threadIdx.x;
    int lane = tid & 31, warp = tid >> 5;
    int wm = warp >> 1, wn = warp & 1;
    int g = lane >> 2, t = lane & 3;
    int m0 = blockIdx.x * 128;

    if (tid < 128) { sbias[tid] = bias[tid]; skey[tid] = 0; }

    int lrow = lane & 15, lkh = lane >> 4;
    uint32_t sAh_u = smem_u32(sAh), sAl_u = smem_u32(sAl);
    uint32_t sBh_u = smem_u32(sBh), sBl_u = smem_u32(sBl);
    uint32_t ahaddr[2], aladdr[2], bhaddr[4], bladdr[4];
    #pragma unroll
    for (int mt = 0; mt < 2; mt++) {
        uint32_t off = 2u * ((wm * 32 + mt * 16 + lrow) * KPAD + lkh * 8);
        ahaddr[mt] = sAh_u + off;
        aladdr[mt] = sAl_u + off;
    }
    #pragma unroll
    for (int j = 0; j < 4; j++) {
        uint32_t off = 2u * ((wn * 64 + j * 16 + lrow) * KPAD + lkh * 8);
        bhaddr[j] = sBh_u + off;
        bladdr[j] = sBl_u + off;
    }

    float acc[2][8][4];
    #pragma unroll
    for (int mt = 0; mt < 2; mt++)
        #pragma unroll
        for (int nt = 0; nt < 8; nt++)
            #pragma unroll
            for (int q = 0; q < 4; q++) acc[mt][nt][q] = 0.f;

    for (int kc = 0; kc < 2; kc++) {
        __syncthreads();
        #pragma unroll
        for (int j = 0; j < 8; j++) {
            int i = tid + j * 256;
            int r = i >> 4, kq = (i & 15) * 4;
            float4 v = *(const float4*)&A[(size_t)(m0 + r) * 128 + kc * 64 + kq];
            float xs[4] = {v.x, v.y, v.z, v.w};
            __nv_bfloat16 h[4], l[4];
            #pragma unroll
            for (int e = 0; e < 4; e++) {
                h[e] = __float2bfloat16(xs[e]);
                l[e] = __float2bfloat16(xs[e] - __bfloat162float(h[e]));
            }
            uint2 hv = make_uint2(pack_bf16(h[0], h[1]), pack_bf16(h[2], h[3]));
            uint2 lv = make_uint2(pack_bf16(l[0], l[1]), pack_bf16(l[2], l[3]));
            *(uint2*)(sAh + r * KPAD + kq) = hv;
            *(uint2*)(sAl + r * KPAD + kq) = lv;
        }
        #pragma unroll
        for (int j = 0; j < 4; j++) {
            int i = tid + j * 256;
            int n = i >> 3, q = i & 7;
            *(uint4*)(sBh + n * KPAD + q * 8) = *(const uint4*)(wthi + n * 128 + kc * 64 + q * 8);
            *(uint4*)(sBl + n * KPAD + q * 8) = *(const uint4*)(wtlo + n * 128 + kc * 64 + q * 8);
        }
        __syncthreads();

        #pragma unroll
        for (int ks = 0; ks < 4; ks++) {
            uint32_t kb = 2u * (ks * 16);
            unsigned ah[2][4], al[2][4];
            #pragma unroll
            for (int mt = 0; mt < 2; mt++) {
                ldmatrix_x4(ah[mt][0], ah[mt][1], ah[mt][2], ah[mt][3], ahaddr[mt] + kb);
                ldmatrix_x4(al[mt][0], al[mt][1], al[mt][2], al[mt][3], aladdr[mt] + kb);
            }
            #pragma unroll
            for (int jh = 0; jh < 2; jh++) {
                unsigned bh[2][4], bl[2][4];
                #pragma unroll
                for (int jj = 0; jj < 2; jj++) {
                    int j = jh * 2 + jj;
                    ldmatrix_x4(bh[jj][0], bh[jj][1], bh[jj][2], bh[jj][3], bhaddr[j] + kb);
                    ldmatrix_x4(bl[jj][0], bl[jj][1], bl[jj][2], bl[jj][3], bladdr[j] + kb);
                }
                #pragma unroll
                for (int jj = 0; jj < 2; jj++) {
                    int j = jh * 2 + jj;
                    #pragma unroll
                    for (int mt = 0; mt < 2; mt++) {
                        MMA_BF16(acc[mt][2 * j],     ah[mt], bh[jj][0], bh[jj][2]);
                        MMA_BF16(acc[mt][2 * j + 1], ah[mt], bh[jj][1], bh[jj][3]);
                        MMA_BF16(acc[mt][2 * j],     ah[mt], bl[jj][0], bl[jj][2]);
                        MMA_BF16(acc[mt][2 * j + 1], ah[mt], bl[jj][1], bl[jj][3]);
                        MMA_BF16(acc[mt][2 * j],     al[mt], bh[jj][0], bh[jj][2]);
                        MMA_BF16(acc[mt][2 * j + 1], al[mt], bh[jj][1], bh[jj][3]);
                    }
                }
            }
        }
    }

    if (WRITE_HT) {
        // epilogue: od * relu(acc + bias), bf16 split, smem transpose -> hT
        __syncthreads();
        __nv_bfloat16* sThi = sm;                   // [128 f][TPAD]
        __nv_bfloat16* sTlo = sm + 128 * TPAD;
        #pragma unroll
        for (int mt = 0; mt < 2; mt++) {
            int ml0 = wm * 32 + mt * 16 + g;
            float od0 = g_od[m0 + ml0];
            float od1 = g_od[m0 + ml0 + 8];
            #pragma unroll
            for (int nt = 0; nt < 8; nt++) {
                int n = wn * 64 + nt * 8 + 2 * t;
                float b0v = sbias[n], b1v = sbias[n + 1];
                float v00 = fmaxf(acc[mt][nt][0] + b0v, 0.f) * od0;
                float v01 = fmaxf(acc[mt][nt][1] + b1v, 0.f) * od0;
                float v10 = fmaxf(acc[mt][nt][2] + b0v, 0.f) * od1;
                float v11 = fmaxf(acc[mt][nt][3] + b1v, 0.f) * od1;
                __nv_bfloat16 h00 = __float2bfloat16(v00);
                __nv_bfloat16 h01 = __float2bfloat16(v01);
                __nv_bfloat16 h10 = __float2bfloat16(v10);
                __nv_bfloat16 h11 = __float2bfloat16(v11);
                sThi[n * TPAD + ml0] = h00;
                sThi[(n + 1) * TPAD + ml0] = h01;
                sThi[n * TPAD + ml0 + 8] = h10;
                sThi[(n + 1) * TPAD + ml0 + 8] = h11;
                sTlo[n * TPAD + ml0] = __float2bfloat16(v00 - __bfloat162float(h00));
                sTlo[(n + 1) * TPAD + ml0] = __float2bfloat16(v01 - __bfloat162float(h01));
                sTlo[n * TPAD + ml0 + 8] = __float2bfloat16(v10 - __bfloat162float(h10));
                sTlo[(n + 1) * TPAD + ml0 + 8] = __float2bfloat16(v11 - __bfloat162float(h11));
            }
        }
        __syncthreads();
        int bg = blockIdx.x >> 1;
        int nb = (blockIdx.x & 1) * 128;
        unsigned* hi32 = (unsigned*)g_hThi;
        unsigned* lo32 = (unsigned*)g_hTlo;
        #pragma unroll
        for (int j = 0; j < 32; j++) {
            int i = tid + j * 256;                   // 0..8191
            int f = i >> 6, np = i & 63;
            unsigned hv = *(unsigned*)&sThi[f * TPAD + 2 * np];
            unsigned lv = *(unsigned*)&sTlo[f * TPAD + 2 * np];
            size_t o = (((size_t)bg * DFEAT + f) * NNODE + nb + 2 * np) >> 1;
            hi32[o] = hv;
            lo32[o] = lv;
        }
    } else {
        // epilogue: fp32 C store + fused row-max key
        __syncthreads();   // skey init visible
        #pragma unroll
        for (int mt = 0; mt < 2; mt++) {
            int m = m0 + wm * 32 + mt * 16 + g;
            float mx0 = 0.f, mx1 = 0.f;
            #pragma unroll
            for (int nt = 0; nt < 8; nt++) {
                int n = wn * 64 + nt * 8 + 2 * t;
                float b0v = sbias[n], b1v = sbias[n + 1];
                float2 o0, o1;
                o0.x = fmaxf(acc[mt][nt][0] + b0v, 0.f);
                o0.y = fmaxf(acc[mt][nt][1] + b1v, 0.f);
                o1.x = fmaxf(acc[mt][nt][2] + b0v, 0.f);
                o1.y = fmaxf(acc[mt][nt][3] + b1v, 0.f);
                mx0 = fmaxf(mx0, fmaxf(o0.x, o0.y));
                mx1 = fmaxf(mx1, fmaxf(o1.x, o1.y));
                *(float2*)&C[(size_t)m * 128 + n] = o0;
                *(float2*)&C[(size_t)(m + 8) * 128 + n] = o1;
            }
            atomicMax(&skey[wm * 32 + mt * 16 + g], __float_as_int(mx0));
            atomicMax(&skey[wm * 32 + mt * 16 + g + 8], __float_as_int(mx1));
        }
        __syncthreads();
        if (tid < 128) g_key[m0 + tid] = __int_as_float(skey[tid]);
    }
}

// =============================================================================
// kernel 6: fused tail — topk (warp 0) + bitonic sort of 10 rows + conv head.
// (validated in R13)
// =============================================================================
__global__ void tail_kernel(const float* __restrict__ w1, const float* __restrict__ b1c,
                            const float* __restrict__ w2, const float* __restrict__ b2c,
                            float* __restrict__ out)
{
    int b = blockIdx.x;
    int tid = threadIdx.x;   // 256
    __shared__ int stopk[KTOP];
    __shared__ float sp[KTOP][132];
    __shared__ float sw1[64][132];
    __shared__ float sc1[64][KTOP];
    __shared__ float sc1p[64][5];

    if (tid < 32) {
        int lane = tid;
        float v[8];
        #pragma unroll
        for (int r = 0; r < 8; r++) v[r] = g_key[b * NNODE + r * 32 + lane];
        for (int t = 0; t < KTOP; t++) {
            float bv = -INFINITY;
            int bi = 0;
            #pragma unroll
            for (int r = 0; r < 8; r++) {
                int idx = r * 32 + lane;
                if (v[r] > bv || (v[r] == bv && idx < bi)) { bv = v[r]; bi = idx; }
            }
            #pragma unroll
            for (int off = 16; off; off >>= 1) {
                float ov = __shfl_xor_sync(FULLMASK, bv, off);
                int   oi = __shfl_xor_sync(FULLMASK, bi, off);
                if (ov > bv || (ov == bv && oi < bi)) { bv = ov; bi = oi; }
            }
            if (lane == 0) stopk[t] = bi;
            if (lane == (bi & 31)) v[bi >> 5] = -INFINITY;
        }
    }
    for (int i = tid; i < 64 * DFEAT; i += 256)
        sw1[i / DFEAT][i % DFEAT] = w1[i];
    __syncthreads();

    int grp = tid >> 7, t7 = tid & 127;
    for (int rr = grp; rr < KTOP; rr += 2) {
        int node = stopk[rr];
        sp[rr][t7] = g_bufB[(size_t)(b * NNODE + node) * DFEAT + t7];
    }
    __syncthreads();

    for (int it = 0; it < 5; it++) {
        int row = grp + 2 * it;
        float* s = &sp[row][0];
        for (int k = 2; k <= 128; k <<= 1) {
            for (int j = k >> 1; j > 0; j >>= 1) {
                int p = t7 ^ j;
                if (p > t7) {
                    bool up = ((t7 & k) == 0);
                    float a = s[t7], c = s[p];
                    if ((a > c) == up) { s[t7] = c; s[p] = a; }
                }
                __syncthreads();
            }
        }
    }

    for (int o = tid; o < 64 * KTOP; o += 256) {
        int oc = o / KTOP, k = o % KTOP;
        float acc = b1c[oc];
        #pragma unroll 8
        for (int d = 0; d < DFEAT; d++) acc += sp[k][d] * sw1[oc][d];
        sc1[oc][k] = fmaxf(acc, 0.f);
    }
    __syncthreads();
    for (int o = tid; o < 64 * 5; o += 256) {
        int ic = o / 5, t = o % 5;
        sc1p[ic][t] = fmaxf(sc1[ic][2 * t], sc1[ic][2 * t + 1]);
    }
    __syncthreads();
    if (tid < 128) {
        float acc = b2c[tid];
        const float* wrow = w2 + tid * 320;
        const float* cp = &sc1p[0][0];
        #pragma unroll 8
        for (int q = 0; q < 320; q++) acc += cp[q] * wrow[q];
        out[b * OUT_CH + tid] = fmaxf(acc, 0.f);
    }
}

// ---------------- launcher ---------------------------------------------------
extern "C" void kernel_launch(void* const* d_in, const int* in_sizes, int n_in,
                              void* d_out, int out_size)
{
    const float* feats   = (const float*)d_in[0];
    const int*   src     = (const int*)d_in[1];
    const int*   dst     = (const int*)d_in[2];
    const float* W0      = (const float*)d_in[3];
    const float* b0      = (const float*)d_in[4];
    const float* W1      = (const float*)d_in[5];
    const float* b1      = (const float*)d_in[6];
    const float* W2      = (const float*)d_in[7];
    const float* b2      = (const float*)d_in[8];
    const float* conv1_w = (const float*)d_in[9];
    const float* conv1_b = (const float*)d_in[10];
    const float* conv2_w = (const float*)d_in[11];
    const float* conv2_b = (const float*)d_in[12];
    float* out = (float*)d_out;

    int build_smem = 128 * 256 * 4;              // 131072
    int agg_smem   = 2 * STAGE_BYTES;            // 110592
    int gemm_smem  = 4 * 128 * KPAD * 2;         // 73728 (>= 2*128*TPAD*2 = 69632)
    cudaFuncSetAttribute(build_kernel, cudaFuncAttributeMaxDynamicSharedMemorySize, build_smem);
    cudaFuncSetAttribute(agg_kernel, cudaFuncAttributeMaxDynamicSharedMemorySize, agg_smem);
    cudaFuncSetAttribute(gemm_bf16_kernel<true>, cudaFuncAttributeMaxDynamicSharedMemorySize, gemm_smem);
    cudaFuncSetAttribute(gemm_bf16_kernel<false>, cudaFuncAttributeMaxDynamicSharedMemorySize, gemm_smem);

    float* bufA;  cudaGetSymbolAddress((void**)&bufA, g_bufA);
    float* bufB;  cudaGetSymbolAddress((void**)&bufB, g_bufB);
    __nv_bfloat16* wthi;  cudaGetSymbolAddress((void**)&wthi, g_Wthi);
    __nv_bfloat16* wtlo;  cudaGetSymbolAddress((void**)&wtlo, g_Wtlo);
    __nv_bfloat16* hthi;  cudaGetSymbolAddress((void**)&hthi, g_hThi);
    __nv_bfloat16* htlo;  cudaGetSymbolAddress((void**)&htlo, g_hTlo);

    build_kernel<<<dim3(BGRAPH, 2), 256, build_smem>>>(src, dst);
    wsplit_kernel<<<192, 256>>>(W0, W1, W2);
    hsplit_kernel<<<BGRAPH, 256>>>(feats);

    dim3 agg_grid(BGRAPH, 2);
    // layer 0
    agg_kernel<<<agg_grid, 256, agg_smem>>>(hthi, htlo, bufA);
    gemm_bf16_kernel<true><<<NUM_NODES / 128, 256, gemm_smem>>>(bufA, wthi, wtlo, b0, nullptr);
    // layer 1
    agg_kernel<<<agg_grid, 256, agg_smem>>>(hthi, htlo, bufA);
    gemm_bf16_kernel<true><<<NUM_NODES / 128, 256, gemm_smem>>>(bufA, wthi + 16384, wtlo + 16384, b1, nullptr);
    // layer 2: fp32 out + fused key
    agg_kernel<<<agg_grid, 256, agg_smem>>>(hthi, htlo, bufA);
    gemm_bf16_kernel<false><<<NUM_NODES / 128, 256, gemm_smem>>>(bufA, wthi + 32768, wtlo + 32768, b2, bufB);

    tail_kernel<<<BGRAPH, 256>>>(conv1_w, conv1_b, conv2_w, conv2_b, out);
}

// round 17
// speedup vs baseline: 1.0904x; 1.0602x over previous
#include <cuda_runtime.h>
#include <cuda_bf16.h>
#include <math.h>
#include <stdint.h>

// Problem constants
#define BGRAPH 256
#define NNODE  256
#define DFEAT  128
#define KTOP   10
#define E_PER  8192
#define NUM_NODES (BGRAPH * NNODE)     // 65536
#define E_TOT (BGRAPH * E_PER)         // 2097152
#define OUT_CH 128
#define FULLMASK 0xffffffffu

// ---------------- scratch (device globals; no runtime allocation) -------------
__device__ float g_bufB[NUM_NODES * DFEAT];                       // fp32 h after layer 2
__device__ float g_od[NUM_NODES];
__device__ float g_id[NUM_NODES];
__device__ __nv_bfloat16 g_adj[(size_t)BGRAPH * NNODE * NNODE];   // 32 MB dense adjacency
// ping-pong hT buffers: fused layer reads [cur], writes [cur^1] (no intra-grid race)
__device__ __nv_bfloat16 g_hThi0[(size_t)NUM_NODES * DFEAT];
__device__ __nv_bfloat16 g_hTlo0[(size_t)NUM_NODES * DFEAT];
__device__ __nv_bfloat16 g_hThi1[(size_t)NUM_NODES * DFEAT];
__device__ __nv_bfloat16 g_hTlo1[(size_t)NUM_NODES * DFEAT];
__device__ float g_key[NUM_NODES];
__device__ __nv_bfloat16 g_Wthi[3 * DFEAT * DFEAT];   // W transposed [n][k], bf16 hi
__device__ __nv_bfloat16 g_Wtlo[3 * DFEAT * DFEAT];   // W transposed [n][k], bf16 lo

__device__ __forceinline__ uint32_t smem_u32(const void* p) {
    uint32_t a;
    asm("{ .reg .u64 t; cvta.to.shared.u64 t, %1; cvt.u32.u64 %0, t; }" : "=r"(a) : "l"(p));
    return a;
}
__device__ __forceinline__ void ldmatrix_x4(unsigned& r0, unsigned& r1, unsigned& r2,
                                            unsigned& r3, uint32_t addr) {
    asm volatile("ldmatrix.sync.aligned.m8n8.x4.shared.b16 {%0,%1,%2,%3}, [%4];"
                 : "=r"(r0), "=r"(r1), "=r"(r2), "=r"(r3) : "r"(addr));
}
__device__ __forceinline__ unsigned pack_bf16(__nv_bfloat16 a, __nv_bfloat16 b) {
    return ((unsigned)__bfloat16_as_ushort(b) << 16) | __bfloat16_as_ushort(a);
}
__device__ __forceinline__ void cp_async16(uint32_t dst, const void* src) {
    asm volatile("cp.async.cg.shared.global [%0], [%1], 16;" :: "r"(dst), "l"(src) : "memory");
}
__device__ __forceinline__ void cp_commit() {
    asm volatile("cp.async.commit_group;" ::: "memory");
}
template <int N>
__device__ __forceinline__ void cp_wait() {
    asm volatile("cp.async.wait_group %0;" :: "n"(N) : "memory");
}

#define MMA_BF16(d, a, b0v, b1v)                                                 \
    asm volatile("mma.sync.aligned.m16n8k16.row.col.f32.bf16.bf16.f32 "          \
                 "{%0,%1,%2,%3}, {%4,%5,%6,%7}, {%8,%9}, {%0,%1,%2,%3};\n"       \
                 : "+f"(d[0]), "+f"(d[1]), "+f"(d[2]), "+f"(d[3])                \
                 : "r"(a[0]), "r"(a[1]), "r"(a[2]), "r"(a[3]), "r"(b0v), "r"(b1v))

#define KPAD 72            // bf16 row stride for 64-k tiles (144B, conflict-free)
#define TPAD 136           // bf16 row stride for 128-k tiles (272B, conflict-free)
#define STAGE_BYTES (2 * (128 * KPAD + 2 * 128 * KPAD))   // 55296
#define FUSED_SMEM (2 * STAGE_BYTES)                      // 110592

// =============================================================================
// kernel 1: graph build via SHARED-memory histogram (unchanged, measured good)
// =============================================================================
__global__ void build_kernel(const int* __restrict__ src, const int* __restrict__ dst) {
    extern __shared__ unsigned scnt[];    // [128][256]
    __shared__ unsigned sdout[256];
    int b = blockIdx.x, dh = blockIdx.y;
    int tid = threadIdx.x;
    int warp = tid >> 5, lane = tid & 31;

    for (int i = tid; i < 128 * 256; i += 256) scnt[i] = 0;
    sdout[tid] = 0;
    __syncthreads();

    int ebase = b * E_PER;
    #pragma unroll 4
    for (int j = 0; j < 32; j++) {
        int e = ebase + j * 256 + tid;
        int s = src[e] & 255;
        int d = dst[e] & 255;
        if (dh == 0) atomicAdd(&sdout[s], 1u);
        if ((d >> 7) == dh) atomicAdd(&scnt[(d & 127) * 256 + s], 1u);
    }
    __syncthreads();

    __nv_bfloat16* adjb = g_adj + (size_t)b * (NNODE * NNODE) + (size_t)dh * 128 * NNODE;
    unsigned* adj32 = (unsigned*)adjb;
    for (int i = tid; i < 128 * 256 / 2; i += 256) {
        unsigned c0 = scnt[2 * i], c1 = scnt[2 * i + 1];
        adj32[i] = pack_bf16(__float2bfloat16((float)c0), __float2bfloat16((float)c1));
    }

    for (int rr = 0; rr < 16; rr++) {
        int row = warp * 16 + rr;
        unsigned ssum = 0;
        #pragma unroll
        for (int q = 0; q < 8; q++) ssum += scnt[row * 256 + q * 32 + lane];
        #pragma unroll
        for (int off = 16; off; off >>= 1) ssum += __shfl_xor_sync(FULLMASK, ssum, off);
        if (lane == 0) {
            int gn = b * NNODE + dh * 128 + row;
            g_id[gn] = 1.0f / sqrtf((float)max((int)ssum, 1));
        }
    }
    if (dh == 0) {
        int gn = b * NNODE + tid;
        g_od[gn] = 1.0f / sqrtf((float)max((int)sdout[tid], 1));
    }
}

// =============================================================================
// kernel 2: hsplit — od*h -> bf16 hi/lo transposed into buffer 0 (feats only)
// =============================================================================
__global__ void hsplit_kernel(const float* __restrict__ h) {
    __shared__ float sh[64][132];
    int b = blockIdx.x;
    int tid = threadIdx.x;
    int gbase = b * NNODE;
    unsigned* hi32 = (unsigned*)g_hThi0;
    unsigned* lo32 = (unsigned*)g_hTlo0;

    for (int c = 0; c < 4; c++) {
        __syncthreads();
        #pragma unroll
        for (int j = 0; j < 8; j++) {
            int i = tid + j * 256;
            int node = i >> 5, f4 = i & 31;
            float od = g_od[gbase + c * 64 + node];
            float4 v = *(const float4*)&h[(size_t)(gbase + c * 64 + node) * DFEAT + f4 * 4];
            sh[node][f4 * 4 + 0] = v.x * od;
            sh[node][f4 * 4 + 1] = v.y * od;
            sh[node][f4 * 4 + 2] = v.z * od;
            sh[node][f4 * 4 + 3] = v.w * od;
        }
        __syncthreads();
        #pragma unroll
        for (int j = 0; j < 16; j++) {
            int i = tid + j * 256;
            int f = i >> 5, np = i & 31;
            float x0 = sh[2 * np][f], x1 = sh[2 * np + 1][f];
            __nv_bfloat16 h0 = __float2bfloat16(x0);
            __nv_bfloat16 h1 = __float2bfloat16(x1);
            size_t o = (((size_t)b * DFEAT + f) * NNODE + c * 64 + 2 * np) >> 1;
            hi32[o] = pack_bf16(h0, h1);
            __nv_bfloat16 l0 = __float2bfloat16(x0 - __bfloat162float(h0));
            __nv_bfloat16 l1 = __float2bfloat16(x1 - __bfloat162float(h1));
            lo32[o] = pack_bf16(l0, l1);
        }
    }
}

// =============================================================================
// kernel 3: W -> W^T bf16 hi/lo split (one launch, all 3 layers)
// =============================================================================
__global__ void wsplit_kernel(const float* __restrict__ W0, const float* __restrict__ W1,
                              const float* __restrict__ W2) {
    int layer = blockIdx.x >> 6;
    int i = (blockIdx.x & 63) * 256 + threadIdx.x;   // i = k*128 + n
    const float* W = (layer == 0) ? W0 : ((layer == 1) ? W1 : W2);
    float x = W[i];
    int k = i >> 7, n = i & 127;
    __nv_bfloat16 hi = __float2bfloat16(x);
    __nv_bfloat16 lo = __float2bfloat16(x - __bfloat162float(hi));
    g_Wthi[layer * 16384 + n * 128 + k] = hi;
    g_Wtlo[layer * 16384 + n * 128 + k] = lo;
}

// =============================================================================
// kernel 4: FUSED layer — agg (cp.async pipelined bf16 MMA) -> smem A' -> gemm.
// Reads hT from [in] buffers, writes next hT to [out] buffers (ping-pong; no
// intra-grid race: input/output arrays disjoint, launch boundary orders layers).
// =============================================================================
template <bool WRITE_HT>
__global__ void __launch_bounds__(256, 2) fused_layer_kernel(
    const __nv_bfloat16* __restrict__ hThi, const __nv_bfloat16* __restrict__ hTlo,
    __nv_bfloat16* __restrict__ outHi, __nv_bfloat16* __restrict__ outLo,
    const __nv_bfloat16* __restrict__ wthi, const __nv_bfloat16* __restrict__ wtlo,
    const float* __restrict__ bias, float* __restrict__ C)
{
    extern __shared__ __nv_bfloat16 sm[];
    __shared__ float sbias[128];
    __shared__ int skey[128];

    int b = blockIdx.x, mh = blockIdx.y;
    int tid = threadIdx.x;
    int lane = tid & 31, warp = tid >> 5;
    int g = lane >> 2, t = lane & 3;
    int gbase = b * NNODE;
    int m0 = gbase + mh * 128;     // global row base of this block

    if (tid < 128) { sbias[tid] = bias[tid]; skey[tid] = 0; }

    // ---------------- phase 1: aggregation ----------------
    int wmA = warp >> 2, wnA = warp & 3;     // 64 M x 32 N warp tile
    const __nv_bfloat16* adjb = g_adj + (size_t)b * (NNODE * NNODE) + (size_t)mh * 128 * NNODE;
    const __nv_bfloat16* bhg = hThi + (size_t)b * DFEAT * NNODE;
    const __nv_bfloat16* blg = hTlo + (size_t)b * DFEAT * NNODE;

    uint32_t sbase = smem_u32(sm);
    const uint32_t BOFF = 2u * 128 * KPAD;
    const uint32_t LOFF = BOFF + 2u * 128 * KPAD;

    int ar = tid >> 3, aq = tid & 7;
    int bn = tid >> 3, bq = tid & 7;

    int lrow = lane & 15, lkh = lane >> 4;
    uint32_t aaddr[4], bhaddr[2], bladdr[2];
    #pragma unroll
    for (int mt = 0; mt < 4; mt++)
        aaddr[mt] = sbase + 2u * ((wmA * 64 + mt * 16 + lrow) * KPAD + lkh * 8);
    #pragma unroll
    for (int j = 0; j < 2; j++) {
        bhaddr[j] = sbase + BOFF + 2u * ((wnA * 32 + j * 16 + lrow) * KPAD + lkh * 8);
        bladdr[j] = sbase + LOFF + 2u * ((wnA * 32 + j * 16 + lrow) * KPAD + lkh * 8);
    }

    float acc[4][4][4];
    #pragma unroll
    for (int mt = 0; mt < 4; mt++)
        #pragma unroll
        for (int nt = 0; nt < 4; nt++)
            #pragma unroll
            for (int q = 0; q < 4; q++) acc[mt][nt][q] = 0.f;

    #define ISSUE_STAGE(st, kc) do {                                              \
        uint32_t s0 = sbase + (uint32_t)(st) * STAGE_BYTES;                       \
        _Pragma("unroll")                                                         \
        for (int j = 0; j < 4; j++) {                                             \
            int r = ar + j * 32;                                                  \
            cp_async16(s0 + 2u * (r * KPAD + aq * 8),                             \
                       adjb + (size_t)r * NNODE + (kc) * 64 + aq * 8);            \
        }                                                                         \
        _Pragma("unroll")                                                         \
        for (int j = 0; j < 4; j++) {                                             \
            int n = bn + j * 32;                                                  \
            cp_async16(s0 + BOFF + 2u * (n * KPAD + bq * 8),                      \
                       bhg + (size_t)n * NNODE + (kc) * 64 + bq * 8);             \
            cp_async16(s0 + LOFF + 2u * (n * KPAD + bq * 8),                      \
                       blg + (size_t)n * NNODE + (kc) * 64 + bq * 8);             \
        }                                                                         \
        cp_commit();                                                              \
    } while (0)

    ISSUE_STAGE(0, 0);
    for (int kc = 0; kc < 4; kc++) {
        int cur = kc & 1;
        if (kc < 3) {
            ISSUE_STAGE(cur ^ 1, kc + 1);
            cp_wait<1>();
        } else {
            cp_wait<0>();
        }
        __syncthreads();
        uint32_t so = (uint32_t)cur * STAGE_BYTES;

        #pragma unroll
        for (int ks = 0; ks < 4; ks++) {
            uint32_t kb = so + 2u * (ks * 16);
            unsigned a[4][4];
            #pragma unroll
            for (int mt = 0; mt < 4; mt++)
                ldmatrix_x4(a[mt][0], a[mt][1], a[mt][2], a[mt][3], aaddr[mt] + kb);
            unsigned bh[2][4], bl[2][4];
            #pragma unroll
            for (int j = 0; j < 2; j++) {
                ldmatrix_x4(bh[j][0], bh[j][1], bh[j][2], bh[j][3], bhaddr[j] + kb);
                ldmatrix_x4(bl[j][0], bl[j][1], bl[j][2], bl[j][3], bladdr[j] + kb);
            }
            #pragma unroll
            for (int j = 0; j < 2; j++) {
                #pragma unroll
                for (int mt = 0; mt < 4; mt++) {
                    MMA_BF16(acc[mt][2 * j],     a[mt], bh[j][0], bh[j][2]);
                    MMA_BF16(acc[mt][2 * j + 1], a[mt], bh[j][1], bh[j][3]);
                    MMA_BF16(acc[mt][2 * j],     a[mt], bl[j][0], bl[j][2]);
                    MMA_BF16(acc[mt][2 * j + 1], a[mt], bl[j][1], bl[j][3]);
                }
            }
        }
        __syncthreads();
    }
    #undef ISSUE_STAGE

    // ---------------- phase 2: id*acc -> bf16 hi/lo smem A' [m][TPAD] --------
    __nv_bfloat16* sAp_hi = sm;                         // 128*TPAD bf16 = 34816 B
    __nv_bfloat16* sAp_lo = sm + 128 * TPAD;
    #pragma unroll
    for (int mt = 0; mt < 4; mt++) {
        int ml = wmA * 64 + mt * 16 + g;
        float id0 = g_id[m0 + ml];
        float id1 = g_id[m0 + ml + 8];
        #pragma unroll
        for (int nt = 0; nt < 4; nt++) {
            int n = wnA * 32 + nt * 8 + 2 * t;
            float v00 = acc[mt][nt][0] * id0, v01 = acc[mt][nt][1] * id0;
            float v10 = acc[mt][nt][2] * id1, v11 = acc[mt][nt][3] * id1;
            __nv_bfloat16 h00 = __float2bfloat16(v00);
            __nv_bfloat16 h01 = __float2bfloat16(v01);
            __nv_bfloat16 h10 = __float2bfloat16(v10);
            __nv_bfloat16 h11 = __float2bfloat16(v11);
            *(unsigned*)&sAp_hi[ml * TPAD + n] = pack_bf16(h00, h01);
            *(unsigned*)&sAp_hi[(ml + 8) * TPAD + n] = pack_bf16(h10, h11);
            *(unsigned*)&sAp_lo[ml * TPAD + n] =
                pack_bf16(__float2bfloat16(v00 - __bfloat162float(h00)),
                          __float2bfloat16(v01 - __bfloat162float(h01)));
            *(unsigned*)&sAp_lo[(ml + 8) * TPAD + n] =
                pack_bf16(__float2bfloat16(v10 - __bfloat162float(h10)),
                          __float2bfloat16(v11 - __bfloat162float(h11)));
        }
    }
    __syncthreads();

    // ---------------- phase 3: gemm A' @ W^T (3-pass) -------------------------
    int wmG = warp >> 1, wnG = warp & 1;     // 32 M x 64 N warp tile
    __nv_bfloat16* sBh = sm + 2 * 128 * TPAD;
    __nv_bfloat16* sBl = sBh + 128 * KPAD;
    uint32_t sAp_hi_u = smem_u32(sAp_hi), sAp_lo_u = smem_u32(sAp_lo);
    uint32_t sBh_u = smem_u32(sBh), sBl_u = smem_u32(sBl);

    uint32_t gah[2], gal[2], gbh[4], gbl[4];
    #pragma unroll
    for (int mt = 0; mt < 2; mt++) {
        uint32_t off = 2u * ((wmG * 32 + mt * 16 + lrow) * TPAD + lkh * 8);
        gah[mt] = sAp_hi_u + off;
        gal[mt] = sAp_lo_u + off;
    }
    #pragma unroll
    for (int j = 0; j < 4; j++) {
        uint32_t off = 2u * ((wnG * 64 + j * 16 + lrow) * KPAD + lkh * 8);
        gbh[j] = sBh_u + off;
        gbl[j] = sBl_u + off;
    }

    float accG[2][8][4];
    #pragma unroll
    for (int mt = 0; mt < 2; mt++)
        #pragma unroll
        for (int nt = 0; nt < 8; nt++)
            #pragma unroll
            for (int q = 0; q < 4; q++) accG[mt][nt][q] = 0.f;

    for (int kc = 0; kc < 2; kc++) {
        __syncthreads();
        #pragma unroll
        for (int j = 0; j < 4; j++) {
            int i = tid + j * 256;
            int n = i >> 3, q = i & 7;
            *(uint4*)(sBh + n * KPAD + q * 8) = *(const uint4*)(wthi + n * 128 + kc * 64 + q * 8);
            *(uint4*)(sBl + n * KPAD + q * 8) = *(const uint4*)(wtlo + n * 128 + kc * 64 + q * 8);
        }
        __syncthreads();

        #pragma unroll
        for (int ks = 0; ks < 4; ks++) {
            uint32_t kba = 2u * (kc * 64 + ks * 16);   // A': full-K stride TPAD
            uint32_t kbb = 2u * (ks * 16);             // W:  chunk-K stride KPAD
            unsigned ah[2][4], al[2][4];
            #pragma unroll
            for (int mt = 0; mt < 2; mt++) {
                ldmatrix_x4(ah[mt][0], ah[mt][1], ah[mt][2], ah[mt][3], gah[mt] + kba);
                ldmatrix_x4(al[mt][0], al[mt][1], al[mt][2], al[mt][3], gal[mt] + kba);
            }
            #pragma unroll
            for (int jh = 0; jh < 2; jh++) {
                unsigned bh[2][4], bl[2][4];
                #pragma unroll
                for (int jj = 0; jj < 2; jj++) {
                    int j = jh * 2 + jj;
                    ldmatrix_x4(bh[jj][0], bh[jj][1], bh[jj][2], bh[jj][3], gbh[j] + kbb);
                    ldmatrix_x4(bl[jj][0], bl[jj][1], bl[jj][2], bl[jj][3], gbl[j] + kbb);
                }
                #pragma unroll
                for (int jj = 0; jj < 2; jj++) {
                    int j = jh * 2 + jj;
                    #pragma unroll
                    for (int mt = 0; mt < 2; mt++) {
                        MMA_BF16(accG[mt][2 * j],     ah[mt], bh[jj][0], bh[jj][2]);
                        MMA_BF16(accG[mt][2 * j + 1], ah[mt], bh[jj][1], bh[jj][3]);
                        MMA_BF16(accG[mt][2 * j],     ah[mt], bl[jj][0], bl[jj][2]);
                        MMA_BF16(accG[mt][2 * j + 1], ah[mt], bl[jj][1], bl[jj][3]);
                        MMA_BF16(accG[mt][2 * j],     al[mt], bh[jj][0], bh[jj][2]);
                        MMA_BF16(accG[mt][2 * j + 1], al[mt], bh[jj][1], bh[jj][3]);
                    }
                }
            }
        }
    }

    // ---------------- phase 4: epilogue --------------------------------------
    if (WRITE_HT) {
        __syncthreads();
        __nv_bfloat16* sThi = sm;                   // [128 f][TPAD]
        __nv_bfloat16* sTlo = sm + 128 * TPAD;
        #pragma unroll
        for (int mt = 0; mt < 2; mt++) {
            int ml0 = wmG * 32 + mt * 16 + g;
            float od0 = g_od[m0 + ml0];
            float od1 = g_od[m0 + ml0 + 8];
            #pragma unroll
            for (int nt = 0; nt < 8; nt++) {
                int n = wnG * 64 + nt * 8 + 2 * t;
                float b0v = sbias[n], b1v = sbias[n + 1];
                float v00 = fmaxf(accG[mt][nt][0] + b0v, 0.f) * od0;
                float v01 = fmaxf(accG[mt][nt][1] + b1v, 0.f) * od0;
                float v10 = fmaxf(accG[mt][nt][2] + b0v, 0.f) * od1;
                float v11 = fmaxf(accG[mt][nt][3] + b1v, 0.f) * od1;
                __nv_bfloat16 h00 = __float2bfloat16(v00);
                __nv_bfloat16 h01 = __float2bfloat16(v01);
                __nv_bfloat16 h10 = __float2bfloat16(v10);
                __nv_bfloat16 h11 = __float2bfloat16(v11);
                sThi[n * TPAD + ml0] = h00;
                sThi[(n + 1) * TPAD + ml0] = h01;
                sThi[n * TPAD + ml0 + 8] = h10;
                sThi[(n + 1) * TPAD + ml0 + 8] = h11;
                sTlo[n * TPAD + ml0] = __float2bfloat16(v00 - __bfloat162float(h00));
                sTlo[(n + 1) * TPAD + ml0] = __float2bfloat16(v01 - __bfloat162float(h01));
                sTlo[n * TPAD + ml0 + 8] = __float2bfloat16(v10 - __bfloat162float(h10));
                sTlo[(n + 1) * TPAD + ml0 + 8] = __float2bfloat16(v11 - __bfloat162float(h11));
            }
        }
        __syncthreads();
        int nb = mh * 128;
        unsigned* hi32 = (unsigned*)outHi;
        unsigned* lo32 = (unsigned*)outLo;
        #pragma unroll
        for (int j = 0; j < 32; j++) {
            int i = tid + j * 256;                   // 0..8191 = 128 f x 64 node-pairs
            int f = i >> 6, np = i & 63;
            unsigned hv = *(unsigned*)&sThi[f * TPAD + 2 * np];
            unsigned lv = *(unsigned*)&sTlo[f * TPAD + 2 * np];
            size_t o = (((size_t)b * DFEAT + f) * NNODE + nb + 2 * np) >> 1;
            hi32[o] = hv;
            lo32[o] = lv;
        }
    } else {
        __syncthreads();   // skey init visible
        #pragma unroll
        for (int mt = 0; mt < 2; mt++) {
            int m = m0 + wmG * 32 + mt * 16 + g;
            float mx0 = 0.f, mx1 = 0.f;
            #pragma unroll
            for (int nt = 0; nt < 8; nt++) {
                int n = wnG * 64 + nt * 8 + 2 * t;
                float b0v = sbias[n], b1v = sbias[n + 1];
                float2 o0, o1;
                o0.x = fmaxf(accG[mt][nt][0] + b0v, 0.f);
                o0.y = fmaxf(accG[mt][nt][1] + b1v, 0.f);
                o1.x = fmaxf(accG[mt][nt][2] + b0v, 0.f);
                o1.y = fmaxf(accG[mt][nt][3] + b1v, 0.f);
                mx0 = fmaxf(mx0, fmaxf(o0.x, o0.y));
                mx1 = fmaxf(mx1, fmaxf(o1.x, o1.y));
                *(float2*)&C[(size_t)m * 128 + n] = o0;
                *(float2*)&C[(size_t)(m + 8) * 128 + n] = o1;
            }
            atomicMax(&skey[wmG * 32 + mt * 16 + g], __float_as_int(mx0));
            atomicMax(&skey[wmG * 32 + mt * 16 + g + 8], __float_as_int(mx1));
        }
        __syncthreads();
        if (tid < 128) g_key[m0 + tid] = __int_as_float(skey[tid]);
    }
}

// =============================================================================
// kernel 5: fused tail — topk (warp 0) + bitonic sort of 10 rows + conv head.
// =============================================================================
__global__ void tail_kernel(const float* __restrict__ w1, const float* __restrict__ b1c,
                            const float* __restrict__ w2, const float* __restrict__ b2c,
                            float* __restrict__ out)
{
    int b = blockIdx.x;
    int tid = threadIdx.x;   // 256
    __shared__ int stopk[KTOP];
    __shared__ float sp[KTOP][132];
    __shared__ float sw1[64][132];
    __shared__ float sc1[64][KTOP];
    __shared__ float sc1p[64][5];

    if (tid < 32) {
        int lane = tid;
        float v[8];
        #pragma unroll
        for (int r = 0; r < 8; r++) v[r] = g_key[b * NNODE + r * 32 + lane];
        for (int t = 0; t < KTOP; t++) {
            float bv = -INFINITY;
            int bi = 0;
            #pragma unroll
            for (int r = 0; r < 8; r++) {
                int idx = r * 32 + lane;
                if (v[r] > bv || (v[r] == bv && idx < bi)) { bv = v[r]; bi = idx; }
            }
            #pragma unroll
            for (int off = 16; off; off >>= 1) {
                float ov = __shfl_xor_sync(FULLMASK, bv, off);
                int   oi = __shfl_xor_sync(FULLMASK, bi, off);
                if (ov > bv || (ov == bv && oi < bi)) { bv = ov; bi = oi; }
            }
            if (lane == 0) stopk[t] = bi;
            if (lane == (bi & 31)) v[bi >> 5] = -INFINITY;
        }
    }
    for (int i = tid; i < 64 * DFEAT; i += 256)
        sw1[i / DFEAT][i % DFEAT] = w1[i];
    __syncthreads();

    int grp = tid >> 7, t7 = tid & 127;
    for (int rr = grp; rr < KTOP; rr += 2) {
        int node = stopk[rr];
        sp[rr][t7] = g_bufB[(size_t)(b * NNODE + node) * DFEAT + t7];
    }
    __syncthreads();

    for (int it = 0; it < 5; it++) {
        int row = grp + 2 * it;
        float* s = &sp[row][0];
        for (int k = 2; k <= 128; k <<= 1) {
            for (int j = k >> 1; j > 0; j >>= 1) {
                int p = t7 ^ j;
                if (p > t7) {
                    bool up = ((t7 & k) == 0);
                    float a = s[t7], c = s[p];
                    if ((a > c) == up) { s[t7] = c; s[p] = a; }
                }
                __syncthreads();
            }
        }
    }

    for (int o = tid; o < 64 * KTOP; o += 256) {
        int oc = o / KTOP, k = o % KTOP;
        float acc = b1c[oc];
        #pragma unroll 8
        for (int d = 0; d < DFEAT; d++) acc += sp[k][d] * sw1[oc][d];
        sc1[oc][k] = fmaxf(acc, 0.f);
    }
    __syncthreads();
    for (int o = tid; o < 64 * 5; o += 256) {
        int ic = o / 5, t = o % 5;
        sc1p[ic][t] = fmaxf(sc1[ic][2 * t], sc1[ic][2 * t + 1]);
    }
    __syncthreads();
    if (tid < 128) {
        float acc = b2c[tid];
        const float* wrow = w2 + tid * 320;
        const float* cp = &sc1p[0][0];
        #pragma unroll 8
        for (int q = 0; q < 320; q++) acc += cp[q] * wrow[q];
        out[b * OUT_CH + tid] = fmaxf(acc, 0.f);
    }
}

// ---------------- launcher ---------------------------------------------------
extern "C" void kernel_launch(void* const* d_in, const int* in_sizes, int n_in,
                              void* d_out, int out_size)
{
    const float* feats   = (const float*)d_in[0];
    const int*   src     = (const int*)d_in[1];
    const int*   dst     = (const int*)d_in[2];
    const float* W0      = (const float*)d_in[3];
    const float* b0      = (const float*)d_in[4];
    const float* W1      = (const float*)d_in[5];
    const float* b1      = (const float*)d_in[6];
    const float* W2      = (const float*)d_in[7];
    const float* b2      = (const float*)d_in[8];
    const float* conv1_w = (const float*)d_in[9];
    const float* conv1_b = (const float*)d_in[10];
    const float* conv2_w = (const float*)d_in[11];
    const float* conv2_b = (const float*)d_in[12];
    float* out = (float*)d_out;

    int build_smem = 128 * 256 * 4;              // 131072
    cudaFuncSetAttribute(build_kernel, cudaFuncAttributeMaxDynamicSharedMemorySize, build_smem);
    cudaFuncSetAttribute(fused_layer_kernel<true>, cudaFuncAttributeMaxDynamicSharedMemorySize, FUSED_SMEM);
    cudaFuncSetAttribute(fused_layer_kernel<false>, cudaFuncAttributeMaxDynamicSharedMemorySize, FUSED_SMEM);

    float* bufB;  cudaGetSymbolAddress((void**)&bufB, g_bufB);
    __nv_bfloat16* wthi;  cudaGetSymbolAddress((void**)&wthi, g_Wthi);
    __nv_bfloat16* wtlo;  cudaGetSymbolAddress((void**)&wtlo, g_Wtlo);
    __nv_bfloat16* hthi0; cudaGetSymbolAddress((void**)&hthi0, g_hThi0);
    __nv_bfloat16* htlo0; cudaGetSymbolAddress((void**)&htlo0, g_hTlo0);
    __nv_bfloat16* hthi1; cudaGetSymbolAddress((void**)&hthi1, g_hThi1);
    __nv_bfloat16* htlo1; cudaGetSymbolAddress((void**)&htlo1, g_hTlo1);

    build_kernel<<<dim3(BGRAPH, 2), 256, build_smem>>>(src, dst);
    wsplit_kernel<<<192, 256>>>(W0, W1, W2);
    hsplit_kernel<<<BGRAPH, 256>>>(feats);   // writes buffer 0

    dim3 grid(BGRAPH, 2);
    // layer 0: read buf0, write buf1
    fused_layer_kernel<true><<<grid, 256, FUSED_SMEM>>>(
        hthi0, htlo0, hthi1, htlo1, wthi, wtlo, b0, nullptr);
    // layer 1: read buf1, write buf0
    fused_layer_kernel<true><<<grid, 256, FUSED_SMEM>>>(
        hthi1, htlo1, hthi0, htlo0, wthi + 16384, wtlo + 16384, b1, nullptr);
    // layer 2: read buf0, write fp32 h + key
    fused_layer_kernel<false><<<grid, 256, FUSED_SMEM>>>(
        hthi0, htlo0, nullptr, nullptr, wthi + 32768, wtlo + 32768, b2, bufB);

    tail_kernel<<<BGRAPH, 256>>>(conv1_w, conv1_b, conv2_w, conv2_b, out);
}